// round 4
// baseline (speedup 1.0000x reference)
#include <cuda_runtime.h>
#include <cstdint>

// BoundingBox: mask [N,1,H,W] fp32 -> bbox [N,4] float32 (ymin, xmin, ymax, xmax),
// hit = (v >= 0.5f). Reference: lo = first hit, hi = last hit + 1; no hit -> (0, full).
//
// One block per image. Four edge probes (row 0, row H-1, col 0, col W-1) issued as
// 4 loads per thread up front (one overlapped DRAM round trip). Hit bits are combined
// with a REAL bitwise-OR reduction (__reduce_or_sync per warp + smem + one barrier) —
// NOT __syncthreads_or, which is a boolean any() and caused round 3's off-by-one.
// If all four edges hit (always true for dense random masks) write {0,0,512,512}.
// Exact edge-inward fallback scans handle arbitrary inputs.

#define BB_H 512
#define BB_W 512
#define BB_THRESH 0.5f
#define BB_NWARP 16

__global__ __launch_bounds__(512, 2)
void BoundingBox_2834678415682_kernel(const float* __restrict__ mask,
                                      float* __restrict__ out) {
    const int n = blockIdx.x;
    const int t = threadIdx.x;
    const int wid = t >> 5;
    const int lid = t & 31;
    const float* __restrict__ img = mask + (size_t)n * BB_H * BB_W;

    __shared__ int warp_bits[BB_NWARP];

    // Front-batched probes: 2 scattered (column edges) + 2 coalesced (row edges).
    float c0 = img[(size_t)t * BB_W];                      // column 0, row t
    float c1 = img[(size_t)t * BB_W + (BB_W - 1)];         // column W-1, row t
    float r0 = img[t];                                     // row 0, col t
    float r1 = img[(size_t)(BB_H - 1) * BB_W + t];         // row H-1, col t

    int v = ((r0 >= BB_THRESH) ? 1 : 0)
          | ((r1 >= BB_THRESH) ? 2 : 0)
          | ((c0 >= BB_THRESH) ? 4 : 0)
          | ((c1 >= BB_THRESH) ? 8 : 0);

    // Bitwise-OR block reduction: warp REDUX, then smem combine.
    int wor = __reduce_or_sync(0xFFFFFFFFu, v);
    if (lid == 0) warp_bits[wid] = wor;
    __syncthreads();

    int agg = 0;
    #pragma unroll
    for (int i = 0; i < BB_NWARP; ++i) agg |= warp_bits[i];  // broadcast LDS, uniform

    if (agg == 0xF) {
        // All four edges hit: bbox is the full image.
        if (t == 0) {
            float4 res = make_float4(0.0f, 0.0f, (float)BB_H, (float)BB_W);
            *reinterpret_cast<float4*>(out + n * 4) = res;
        }
        return;
    }

    // ---- Exact fallback (cold path; agg is block-uniform) ----
    float ymin = 0.0f, xmin = 0.0f, ymax = (float)BB_H, xmax = (float)BB_W;

    // ymin: first row with any hit (row 0 already known: bit0).
    if (!(agg & 1)) {
        for (int r = 1; r < BB_H; ++r) {
            int hit = (img[(size_t)r * BB_W + t] >= BB_THRESH) ? 1 : 0;
            if (__syncthreads_or(hit)) { ymin = (float)r; break; }
        }
        // no hit anywhere -> ymin stays 0 (reference convention)
    }

    // ymax: last row with any hit, +1 (row H-1 known: bit1).
    if (!(agg & 2)) {
        bool found = false;
        for (int r = BB_H - 2; r >= 0; --r) {
            int hit = (img[(size_t)r * BB_W + t] >= BB_THRESH) ? 1 : 0;
            if (__syncthreads_or(hit)) { ymax = (float)(r + 1); found = true; break; }
        }
        if (!found) ymax = (float)BB_H;  // no hit -> full (reference convention)
    }

    // xmin: first column with any hit (col 0 known: bit2).
    if (!(agg & 4)) {
        for (int c = 1; c < BB_W; ++c) {
            int hit = (img[(size_t)t * BB_W + c] >= BB_THRESH) ? 1 : 0;
            if (__syncthreads_or(hit)) { xmin = (float)c; break; }
        }
    }

    // xmax: last column with any hit, +1 (col W-1 known: bit3).
    if (!(agg & 8)) {
        bool found = false;
        for (int c = BB_W - 2; c >= 0; --c) {
            int hit = (img[(size_t)t * BB_W + c] >= BB_THRESH) ? 1 : 0;
            if (__syncthreads_or(hit)) { xmax = (float)(c + 1); found = true; break; }
        }
        if (!found) xmax = (float)BB_W;
    }

    if (t == 0) {
        out[n * 4 + 0] = ymin;
        out[n * 4 + 1] = xmin;
        out[n * 4 + 2] = ymax;
        out[n * 4 + 3] = xmax;
    }
}

extern "C" void kernel_launch(void* const* d_in, const int* in_sizes, int n_in,
                              void* d_out, int out_size) {
    const float* mask = (const float*)d_in[0];
    float* out = (float*)d_out;

    const int N = in_sizes[0] / (BB_H * BB_W);

    BoundingBox_2834678415682_kernel<<<N, 512>>>(mask, out);
}

// round 5
// speedup vs baseline: 1.5704x; 1.5704x over previous
#include <cuda_runtime.h>
#include <cstdint>

// BoundingBox: mask [N,1,H,W] fp32 -> bbox [N,4] float32 (ymin, xmin, ymax, xmax),
// hit = (v >= 0.5f). Reference: lo = first hit, hi = last hit + 1; no hit -> (0, full).
//
// Round-4 ncu showed the kernel is DRAM-traffic bound: probing a full 512-element
// column costs 512 scattered 128B lines (64 KB) per column. Certification doesn't
// need the whole column: scan in 32-element warp batches with ballot early-exit —
// expected 1 batch (32 lines) per column, 1 line per row. 16x traffic reduction.
//
// One warp per (image, direction); no smem, no block barriers. Exact for arbitrary
// inputs (full fallback scan; no-hit conventions match the reference).

#define BB_H 512
#define BB_W 512
#define BB_THRESH 0.5f
#define FULLMASK 0xFFFFFFFFu

__global__ __launch_bounds__(128, 8)
void BoundingBox_2834678415682_kernel(const float* __restrict__ mask,
                                      float* __restrict__ out) {
    const int n    = blockIdx.x;
    const int wid  = threadIdx.x >> 5;   // 0..3 = direction
    const int lane = threadIdx.x & 31;
    const float* __restrict__ img = mask + (size_t)n * BB_H * BB_W;

    if (wid == 0) {
        // ymin: first row with any hit (default 0)
        int result = 0;
        for (int r = 0; r < BB_H; ++r) {
            bool rowhit = false;
            #pragma unroll 1
            for (int k = 0; k < BB_W / 32; ++k) {
                float v = img[(size_t)r * BB_W + k * 32 + lane];
                if (__ballot_sync(FULLMASK, v >= BB_THRESH)) { rowhit = true; break; }
            }
            if (rowhit) { result = r; break; }
        }
        if (lane == 0) out[n * 4 + 0] = (float)result;
    } else if (wid == 1) {
        // xmin: first column with any hit (default 0)
        int result = 0;
        for (int c = 0; c < BB_W; ++c) {
            bool colhit = false;
            #pragma unroll 1
            for (int k = 0; k < BB_H / 32; ++k) {
                float v = img[(size_t)(k * 32 + lane) * BB_W + c];
                if (__ballot_sync(FULLMASK, v >= BB_THRESH)) { colhit = true; break; }
            }
            if (colhit) { result = c; break; }
        }
        if (lane == 0) out[n * 4 + 1] = (float)result;
    } else if (wid == 2) {
        // ymax: last row with any hit, +1 (default H)
        int result = BB_H;
        for (int r = BB_H - 1; r >= 0; --r) {
            bool rowhit = false;
            #pragma unroll 1
            for (int k = 0; k < BB_W / 32; ++k) {
                float v = img[(size_t)r * BB_W + k * 32 + lane];
                if (__ballot_sync(FULLMASK, v >= BB_THRESH)) { rowhit = true; break; }
            }
            if (rowhit) { result = r + 1; break; }
        }
        if (result == 0) result = BB_H;   // unreachable (r=0 hit gives 1), kept for clarity
        if (lane == 0) out[n * 4 + 2] = (float)result;
    } else {
        // xmax: last column with any hit, +1 (default W)
        int result = BB_W;
        for (int c = BB_W - 1; c >= 0; --c) {
            bool colhit = false;
            #pragma unroll 1
            for (int k = 0; k < BB_H / 32; ++k) {
                float v = img[(size_t)(k * 32 + lane) * BB_W + c];
                if (__ballot_sync(FULLMASK, v >= BB_THRESH)) { colhit = true; break; }
            }
            if (colhit) { result = c + 1; break; }
        }
        if (lane == 0) out[n * 4 + 3] = (float)result;
    }
}

extern "C" void kernel_launch(void* const* d_in, const int* in_sizes, int n_in,
                              void* d_out, int out_size) {
    const float* mask = (const float*)d_in[0];
    float* out = (float*)d_out;

    const int N = in_sizes[0] / (BB_H * BB_W);

    BoundingBox_2834678415682_kernel<<<N, 128>>>(mask, out);
}